// round 2
// baseline (speedup 1.0000x reference)
#include <cuda_runtime.h>

#define G 64
#define NCAP 100352
#define ECAP 1605632

// ---------------- device scratch (static; no allocation allowed) ----------------
__device__ int g_idx64;

__device__ int cnt_o[NCAP], cnt_l[NCAP], fill_o[NCAP], fill_l[NCAP];
__device__ int rp_o[NCAP + 1], rp_l[NCAP + 1];
__device__ float dinv_o[NCAP], dinv_l[NCAP];
__device__ float2 csr_o[ECAP], csr_l[ECAP];

__device__ float P1[NCAP * 32];          // A^ x_origin (25 used, stride 32)
__device__ float H1b[NCAP * 128];        // relu(P1 W1 + b1)
__device__ float T2b[NCAP * 64];         // H1 W2
__device__ float H2b[NCAP * 64];         // relu(A^ T2 + b2)
__device__ float T3b[NCAP * 8];          // H2 W5 (5 used, stride 8)
__device__ float H3b[NCAP * 8];          // A^ T3 + b5
__device__ float PLb[NCAP * 52];         // A^ x_line (51 used, stride 52)
__device__ float HL1b[NCAP * 64];        // relu(PL W3 + b3)
__device__ float TLb[NCAP * 8];          // HL1 W4
__device__ float HLb[NCAP * 8];          // A^ TL + b4

__device__ float gsum_o[G * 5], gsum_l[G * 5];
__device__ int gcnt_o[G], gcnt_l[G];

// ---------------- index width handling ----------------
__device__ __forceinline__ int idx_at(const void* p, long long i) {
    if (g_idx64) return (int)((const long long*)p)[i];
    return ((const int*)p)[i];
}

__global__ void detect_kernel(const unsigned* p) {
    if (blockIdx.x == 0 && threadIdx.x == 0) {
        int all0 = 1;
        for (int i = 1; i < 128; i += 2) all0 &= (p[i] == 0u);
        g_idx64 = all0;  // high words of nonneg int64 are all zero
    }
}

// ---------------- init (zero per-launch state) ----------------
__global__ void init_kernel(int N) {
    int i = blockIdx.x * blockDim.x + threadIdx.x;
    int stride = gridDim.x * blockDim.x;
    for (int k = i; k < N; k += stride) {
        cnt_o[k] = 0; cnt_l[k] = 0; fill_o[k] = 0; fill_l[k] = 0;
    }
    if (i < G * 5) { gsum_o[i] = 0.f; gsum_l[i] = 0.f; }
    if (i < G)     { gcnt_o[i] = 0;   gcnt_l[i] = 0; }
}

// ---------------- CSR build ----------------
__global__ void hist_kernel(const void* ei, long long E, int* cnt) {
    long long stride = (long long)gridDim.x * blockDim.x;
    for (long long e = blockIdx.x * (long long)blockDim.x + threadIdx.x; e < E; e += stride) {
        int d = idx_at(ei, E + e);  // dst = row 1
        atomicAdd(&cnt[d], 1);
    }
}

__global__ void dinv_kernel(const int* __restrict__ cnt, float* __restrict__ dinv, int N) {
    int i = blockIdx.x * blockDim.x + threadIdx.x;
    if (i < N) dinv[i] = rsqrtf((float)(cnt[i] + 1));  // +1 self loop
}

__global__ void scan_kernel(const int* __restrict__ cnt, int* __restrict__ rp, int N) {
    __shared__ int wsum[32];
    __shared__ int carry;
    int tid = threadIdx.x, lane = tid & 31, wid = tid >> 5;
    if (tid == 0) carry = 0;
    __syncthreads();
    for (int base = 0; base < N; base += 1024) {
        int i = base + tid;
        int v = (i < N) ? cnt[i] : 0;
        int x = v;
#pragma unroll
        for (int o = 1; o < 32; o <<= 1) {
            int y = __shfl_up_sync(0xffffffffu, x, o);
            if (lane >= o) x += y;
        }
        if (lane == 31) wsum[wid] = x;
        __syncthreads();
        if (wid == 0) {
            int s = wsum[lane];
#pragma unroll
            for (int o = 1; o < 32; o <<= 1) {
                int y = __shfl_up_sync(0xffffffffu, s, o);
                if (lane >= o) s += y;
            }
            wsum[lane] = s;
        }
        __syncthreads();
        int off = carry + (wid > 0 ? wsum[wid - 1] : 0);
        if (i < N) rp[i] = off + x - v;  // exclusive
        __syncthreads();
        if (tid == 0) carry += wsum[31];
        __syncthreads();
    }
    if (tid == 0) rp[N] = carry;
}

__global__ void scatter_kernel(const void* ei, long long E, const int* __restrict__ rp,
                               int* fill, const float* __restrict__ dinv, float2* csr) {
    long long stride = (long long)gridDim.x * blockDim.x;
    for (long long e = blockIdx.x * (long long)blockDim.x + threadIdx.x; e < E; e += stride) {
        int s = idx_at(ei, e);
        int d = idx_at(ei, E + e);
        int pos = rp[d] + atomicAdd(&fill[d], 1);
        csr[pos] = make_float2(__int_as_float(s), dinv[s] * dinv[d]);
    }
}

// ---------------- propagation: out = A^ in (+bias, relu) ----------------
// GROUP lanes cooperate per node; features split across lanes (chunks of GROUP).
template <int GROUP, int F>
__global__ void prop_kernel(const float* __restrict__ hin, int in_stride,
                            float* __restrict__ hout, int out_stride,
                            const int* __restrict__ rp, const float2* __restrict__ csr,
                            const float* __restrict__ dinv, const float* __restrict__ bias,
                            int do_relu, int N) {
    constexpr int CH = (F + GROUP - 1) / GROUP;
    const int gpw = 32 / GROUP;
    int warp = (int)((blockIdx.x * (long long)blockDim.x + threadIdx.x) >> 5);
    int lane = threadIdx.x & 31;
    int node = warp * gpw + lane / GROUP;
    int l = lane % GROUP;
    if (node >= N) return;
    float acc[CH];
#pragma unroll
    for (int c = 0; c < CH; c++) acc[c] = 0.f;
    int e = rp[node], end = rp[node + 1];
    for (; e + 1 < end; e += 2) {
        float2 a = csr[e], b = csr[e + 1];
        const float* r0 = hin + (size_t)__float_as_int(a.x) * in_stride;
        const float* r1 = hin + (size_t)__float_as_int(b.x) * in_stride;
#pragma unroll
        for (int c = 0; c < CH; c++) {
            int f = c * GROUP + l;
            if (f < F) acc[c] += a.y * __ldg(r0 + f) + b.y * __ldg(r1 + f);
        }
    }
    if (e < end) {
        float2 a = csr[e];
        const float* r0 = hin + (size_t)__float_as_int(a.x) * in_stride;
#pragma unroll
        for (int c = 0; c < CH; c++) {
            int f = c * GROUP + l;
            if (f < F) acc[c] += a.y * __ldg(r0 + f);
        }
    }
    float ds = dinv[node];
    float sw = ds * ds;  // self loop weight
#pragma unroll
    for (int c = 0; c < CH; c++) {
        int f = c * GROUP + l;
        if (f < F) {
            float v = acc[c] + sw * hin[(size_t)node * in_stride + f];
            if (bias) v += bias[f];
            if (do_relu) v = fmaxf(v, 0.f);
            hout[(size_t)node * out_stride + f] = v;
        }
    }
}

// ---------------- skinny GEMM: Y[M,NOUT] = X[M,K] @ W[K,NW] (+bias, relu) ----------------
template <int K, int NOUT, int TC, int NW>
__global__ void gemm_kernel(const float* __restrict__ X, int xstride,
                            const float* __restrict__ W, const float* __restrict__ bias,
                            float* __restrict__ Y, int ystride, int do_relu, int M) {
    constexpr int TPR = NOUT / TC;   // threads per row
    constexpr int R = 256 / TPR;     // rows per block
    __shared__ float Ws[K * NOUT];
    for (int i = threadIdx.x; i < K * NOUT; i += 256) {
        int k = i / NOUT, c = i % NOUT;
        Ws[i] = (c < NW) ? W[k * NW + c] : 0.f;
    }
    __syncthreads();
    int r = blockIdx.x * R + threadIdx.x / TPR;
    int c0 = (threadIdx.x % TPR) * TC;
    if (r >= M) return;
    float acc[TC];
#pragma unroll
    for (int t = 0; t < TC; t++) acc[t] = 0.f;
    const float* xrow = X + (size_t)r * xstride;
#pragma unroll 4
    for (int k = 0; k < K; k++) {
        float xv = __ldg(xrow + k);
        if (TC % 4 == 0) {
#pragma unroll
            for (int t = 0; t < TC; t += 4) {
                float4 w = *(const float4*)&Ws[k * NOUT + c0 + t];
                acc[t + 0] += xv * w.x;
                acc[t + 1] += xv * w.y;
                acc[t + 2] += xv * w.z;
                acc[t + 3] += xv * w.w;
            }
        } else {
#pragma unroll
            for (int t = 0; t < TC; t++) acc[t] += xv * Ws[k * NOUT + c0 + t];
        }
    }
#pragma unroll
    for (int t = 0; t < TC; t++) {
        int c = c0 + t;
        float v = acc[t];
        if (bias && c < NW) v += bias[c];
        if (do_relu) v = fmaxf(v, 0.f);
        Y[(size_t)r * ystride + c] = v;
    }
}

// ---------------- per-graph mean pool (sum + count; divide at the end) ----------------
__global__ void pool_kernel(const float* __restrict__ h, int stride, const void* batch,
                            int N, float* gsum, int* gcnt) {
    __shared__ float ss[G * 5];
    __shared__ int sc[G];
    for (int i = threadIdx.x; i < G * 5; i += blockDim.x) ss[i] = 0.f;   // FIX: strided (320 > 256)
    for (int i = threadIdx.x; i < G; i += blockDim.x) sc[i] = 0;
    __syncthreads();
    int stride_t = gridDim.x * blockDim.x;
    for (int i = blockIdx.x * blockDim.x + threadIdx.x; i < N; i += stride_t) {
        int g = idx_at(batch, i);
#pragma unroll
        for (int j = 0; j < 5; j++) atomicAdd(&ss[g * 5 + j], h[(size_t)i * stride + j]);
        atomicAdd(&sc[g], 1);
    }
    __syncthreads();
    for (int i = threadIdx.x; i < G * 5; i += blockDim.x) atomicAdd(&gsum[i], ss[i]);  // FIX
    for (int i = threadIdx.x; i < G; i += blockDim.x) atomicAdd(&gcnt[i], sc[i]);
}

// ---------------- final FC + log_softmax ----------------
__global__ void final_kernel(const float* __restrict__ Wfc, const float* __restrict__ bfc,
                             float* __restrict__ out) {
    int g = threadIdx.x;
    if (g >= G) return;
    float f[10];
    float co = fmaxf((float)gcnt_o[g], 1.f);
    float cl = fmaxf((float)gcnt_l[g], 1.f);
#pragma unroll
    for (int j = 0; j < 5; j++) {
        f[j] = gsum_o[g * 5 + j] / co;
        f[5 + j] = gsum_l[g * 5 + j] / cl;
    }
    float y0 = bfc[0], y1 = bfc[1];
#pragma unroll
    for (int j = 0; j < 10; j++) {
        y0 += f[j] * Wfc[j * 2 + 0];
        y1 += f[j] * Wfc[j * 2 + 1];
    }
    float m = fmaxf(y0, y1);
    float lse = m + logf(expf(y0 - m) + expf(y1 - m));
    out[g * 2 + 0] = y0 - lse;
    out[g * 2 + 1] = y1 - lse;
}

// ---------------- host side ----------------
struct SymPtrs {
    float2 *csr_o_, *csr_l_;
    int *rp_o_, *rp_l_, *cnt_o_, *cnt_l_, *fill_o_, *fill_l_, *gcnt_o_, *gcnt_l_;
    float *dinv_o_, *dinv_l_;
    float *P1_, *H1_, *T2_, *H2_, *T3_, *H3_, *PL_, *HL1_, *TL_, *HL_;
    float *gsum_o_, *gsum_l_;
    bool ready;
};
static SymPtrs SP = {};

static void resolve_syms() {
    if (SP.ready) return;
    cudaGetSymbolAddress((void**)&SP.csr_o_, csr_o);
    cudaGetSymbolAddress((void**)&SP.csr_l_, csr_l);
    cudaGetSymbolAddress((void**)&SP.rp_o_, rp_o);
    cudaGetSymbolAddress((void**)&SP.rp_l_, rp_l);
    cudaGetSymbolAddress((void**)&SP.cnt_o_, cnt_o);
    cudaGetSymbolAddress((void**)&SP.cnt_l_, cnt_l);
    cudaGetSymbolAddress((void**)&SP.fill_o_, fill_o);
    cudaGetSymbolAddress((void**)&SP.fill_l_, fill_l);
    cudaGetSymbolAddress((void**)&SP.gcnt_o_, gcnt_o);
    cudaGetSymbolAddress((void**)&SP.gcnt_l_, gcnt_l);
    cudaGetSymbolAddress((void**)&SP.dinv_o_, dinv_o);
    cudaGetSymbolAddress((void**)&SP.dinv_l_, dinv_l);
    cudaGetSymbolAddress((void**)&SP.P1_, P1);
    cudaGetSymbolAddress((void**)&SP.H1_, H1b);
    cudaGetSymbolAddress((void**)&SP.T2_, T2b);
    cudaGetSymbolAddress((void**)&SP.H2_, H2b);
    cudaGetSymbolAddress((void**)&SP.T3_, T3b);
    cudaGetSymbolAddress((void**)&SP.H3_, H3b);
    cudaGetSymbolAddress((void**)&SP.PL_, PLb);
    cudaGetSymbolAddress((void**)&SP.HL1_, HL1b);
    cudaGetSymbolAddress((void**)&SP.TL_, TLb);
    cudaGetSymbolAddress((void**)&SP.HL_, HLb);
    cudaGetSymbolAddress((void**)&SP.gsum_o_, gsum_o);
    cudaGetSymbolAddress((void**)&SP.gsum_l_, gsum_l);
    SP.ready = true;
}

extern "C" void kernel_launch(void* const* d_in, const int* in_sizes, int n_in,
                              void* d_out, int out_size) {
    resolve_syms();

    const float* x_o = (const float*)d_in[0];
    const void* ei_o = d_in[1];
    const void* ba_o = d_in[2];
    const float* x_l = (const float*)d_in[3];
    const void* ei_l = d_in[4];
    const void* ba_l = d_in[5];
    const float* W1 = (const float*)d_in[6];
    const float* b1 = (const float*)d_in[7];
    const float* W2 = (const float*)d_in[8];
    const float* b2 = (const float*)d_in[9];
    const float* W5 = (const float*)d_in[10];
    const float* b5 = (const float*)d_in[11];
    const float* W3 = (const float*)d_in[12];
    const float* b3 = (const float*)d_in[13];
    const float* W4 = (const float*)d_in[14];
    const float* b4 = (const float*)d_in[15];
    const float* Wfc = (const float*)d_in[16];
    const float* bfc = (const float*)d_in[17];
    float* out = (float*)d_out;

    int N = in_sizes[0] / 25;
    long long E = (long long)in_sizes[1] / 2;

    detect_kernel<<<1, 32>>>((const unsigned*)ei_o);
    init_kernel<<<256, 256>>>(N);

    hist_kernel<<<1024, 256>>>(ei_o, E, SP.cnt_o_);
    hist_kernel<<<1024, 256>>>(ei_l, E, SP.cnt_l_);
    dinv_kernel<<<(N + 255) / 256, 256>>>(SP.cnt_o_, SP.dinv_o_, N);
    dinv_kernel<<<(N + 255) / 256, 256>>>(SP.cnt_l_, SP.dinv_l_, N);
    scan_kernel<<<1, 1024>>>(SP.cnt_o_, SP.rp_o_, N);
    scan_kernel<<<1, 1024>>>(SP.cnt_l_, SP.rp_l_, N);
    scatter_kernel<<<1024, 256>>>(ei_o, E, SP.rp_o_, SP.fill_o_, SP.dinv_o_, SP.csr_o_);
    scatter_kernel<<<1024, 256>>>(ei_l, E, SP.rp_l_, SP.fill_l_, SP.dinv_l_, SP.csr_l_);

    int pb32 = (N * 32 + 255) / 256;  // warp-per-node blocks
    int pb8 = (N + 31) / 32;          // 8-lane-group blocks (4 nodes/warp, 32/block)

    // ---- origin branch ----
    prop_kernel<32, 25><<<pb32, 256>>>(x_o, 25, SP.P1_, 32, SP.rp_o_, SP.csr_o_,
                                       SP.dinv_o_, nullptr, 0, N);
    gemm_kernel<25, 128, 8, 128><<<(N + 15) / 16, 256>>>(SP.P1_, 32, W1, b1, SP.H1_, 128, 1, N);
    gemm_kernel<128, 64, 4, 64><<<(N + 15) / 16, 256>>>(SP.H1_, 128, W2, nullptr, SP.T2_, 64, 0, N);
    prop_kernel<32, 64><<<pb32, 256>>>(SP.T2_, 64, SP.H2_, 64, SP.rp_o_, SP.csr_o_,
                                       SP.dinv_o_, b2, 1, N);
    gemm_kernel<64, 8, 1, 5><<<(N + 31) / 32, 256>>>(SP.H2_, 64, W5, nullptr, SP.T3_, 8, 0, N);
    prop_kernel<8, 5><<<pb8, 256>>>(SP.T3_, 8, SP.H3_, 8, SP.rp_o_, SP.csr_o_,
                                    SP.dinv_o_, b5, 0, N);
    pool_kernel<<<512, 256>>>(SP.H3_, 8, ba_o, N, SP.gsum_o_, SP.gcnt_o_);

    // ---- line branch ----
    prop_kernel<32, 51><<<pb32, 256>>>(x_l, 51, SP.PL_, 52, SP.rp_l_, SP.csr_l_,
                                       SP.dinv_l_, nullptr, 0, N);
    gemm_kernel<51, 64, 4, 64><<<(N + 15) / 16, 256>>>(SP.PL_, 52, W3, b3, SP.HL1_, 64, 1, N);
    gemm_kernel<64, 8, 1, 5><<<(N + 31) / 32, 256>>>(SP.HL1_, 64, W4, nullptr, SP.TL_, 8, 0, N);
    prop_kernel<8, 5><<<pb8, 256>>>(SP.TL_, 8, SP.HL_, 8, SP.rp_l_, SP.csr_l_,
                                    SP.dinv_l_, b4, 0, N);
    pool_kernel<<<512, 256>>>(SP.HL_, 8, ba_l, N, SP.gsum_l_, SP.gcnt_l_);

    final_kernel<<<1, G>>>(Wfc, bfc, out);
}

// round 6
// speedup vs baseline: 1.3981x; 1.3981x over previous
#include <cuda_runtime.h>

#define G 64
#define NCAP 100352
#define ECAP 1605632

// ---------------- device scratch (static; no allocation allowed) ----------------
__device__ int g_idx64;

__device__ int cnt_o[NCAP], cnt_l[NCAP], fill_o[NCAP], fill_l[NCAP];
__device__ int rp_o[NCAP + 1], rp_l[NCAP + 1];
__device__ int bsum_o[256], bsum_l[256];
__device__ float dinv_o[NCAP], dinv_l[NCAP];
__device__ float2 csr_o[ECAP], csr_l[ECAP];

__device__ float P1[NCAP * 32];          // A^ x_origin (25 used, stride 32)
__device__ float H1b[NCAP * 128];        // relu(P1 W1 + b1)
__device__ float T2b[NCAP * 64];         // H1 W2
__device__ float H2b[NCAP * 64];         // relu(A^ T2 + b2)
__device__ float T3b[NCAP * 8];          // H2 W5 (5 used, stride 8)
__device__ float PLb[NCAP * 52];         // A^ x_line (51 used, stride 52)
__device__ float HL1b[NCAP * 64];        // relu(PL W3 + b3)
__device__ float TLb[NCAP * 8];          // HL1 W4

__device__ float gsum_o[G * 5], gsum_l[G * 5];
__device__ int gcnt_o[G], gcnt_l[G];

// ---------------- index width handling ----------------
__device__ __forceinline__ int idx_at(const void* p, long long i) {
    if (g_idx64) return (int)((const long long*)p)[i];
    return ((const int*)p)[i];
}

__global__ void detect_kernel(const unsigned* p) {
    if (blockIdx.x == 0 && threadIdx.x == 0) {
        int all0 = 1;
        for (int i = 1; i < 128; i += 2) all0 &= (p[i] == 0u);
        g_idx64 = all0;  // high words of nonneg int64 are all zero
    }
}

// ---------------- init (zero per-launch state) ----------------
__global__ void init_kernel(int N) {
    int i = blockIdx.x * blockDim.x + threadIdx.x;
    int stride = gridDim.x * blockDim.x;
    for (int k = i; k < N; k += stride) {
        cnt_o[k] = 0; cnt_l[k] = 0; fill_o[k] = 0; fill_l[k] = 0;
    }
    if (i < G * 5) { gsum_o[i] = 0.f; gsum_l[i] = 0.f; }
    if (i < G)     { gcnt_o[i] = 0;   gcnt_l[i] = 0; }
}

// ---------------- CSR build ----------------
__global__ void hist_kernel(const void* ei, long long E, int* cnt) {
    long long stride = (long long)gridDim.x * blockDim.x;
    for (long long e = blockIdx.x * (long long)blockDim.x + threadIdx.x; e < E; e += stride) {
        int d = idx_at(ei, E + e);  // dst = row 1
        atomicAdd(&cnt[d], 1);
    }
}

// scan phase 1: per-1024-block sums (+ fused dinv)
__global__ void scan1_kernel(const int* __restrict__ cnt, float* __restrict__ dinv,
                             int* __restrict__ bsum, int N) {
    __shared__ int wsum[32];
    int tid = threadIdx.x, lane = tid & 31, wid = tid >> 5;
    int i = blockIdx.x * 1024 + tid;
    int v = (i < N) ? cnt[i] : 0;
    if (i < N) dinv[i] = rsqrtf((float)(v + 1));
    int x = v;
#pragma unroll
    for (int o = 16; o > 0; o >>= 1) x += __shfl_down_sync(0xffffffffu, x, o);
    if (lane == 0) wsum[wid] = x;
    __syncthreads();
    if (wid == 0) {
        int s = wsum[lane];
#pragma unroll
        for (int o = 16; o > 0; o >>= 1) s += __shfl_down_sync(0xffffffffu, s, o);
        if (lane == 0) bsum[blockIdx.x] = s;
    }
}

// scan phase 2: exclusive scan of <=128 block sums (in place), set rp[N]
__global__ void scan2_kernel(int* __restrict__ bsum, int* __restrict__ rp, int B, int N) {
    __shared__ int ws[4];
    int tid = threadIdx.x, lane = tid & 31, wid = tid >> 5;
    int v = (tid < B) ? bsum[tid] : 0;
    int x = v;
#pragma unroll
    for (int o = 1; o < 32; o <<= 1) {
        int y = __shfl_up_sync(0xffffffffu, x, o);
        if (lane >= o) x += y;
    }
    if (lane == 31) ws[wid] = x;
    __syncthreads();
    int add = 0;
    for (int w = 0; w < wid; w++) add += ws[w];
    x += add;
    if (tid < B) bsum[tid] = x - v;   // exclusive
    if (tid == B - 1) rp[N] = x;      // total
}

// scan phase 3: local exclusive scan + block offset
__global__ void scan3_kernel(const int* __restrict__ cnt, const int* __restrict__ boff,
                             int* __restrict__ rp, int N) {
    __shared__ int wsum[32];
    int tid = threadIdx.x, lane = tid & 31, wid = tid >> 5;
    int i = blockIdx.x * 1024 + tid;
    int v = (i < N) ? cnt[i] : 0;
    int x = v;
#pragma unroll
    for (int o = 1; o < 32; o <<= 1) {
        int y = __shfl_up_sync(0xffffffffu, x, o);
        if (lane >= o) x += y;
    }
    if (lane == 31) wsum[wid] = x;
    __syncthreads();
    if (wid == 0) {
        int s = wsum[lane];
#pragma unroll
        for (int o = 1; o < 32; o <<= 1) {
            int y = __shfl_up_sync(0xffffffffu, s, o);
            if (lane >= o) s += y;
        }
        wsum[lane] = s;
    }
    __syncthreads();
    int off = boff[blockIdx.x] + (wid > 0 ? wsum[wid - 1] : 0);
    if (i < N) rp[i] = off + x - v;
}

__global__ void scatter_kernel(const void* ei, long long E, const int* __restrict__ rp,
                               int* fill, const float* __restrict__ dinv, float2* csr) {
    long long stride = (long long)gridDim.x * blockDim.x;
    for (long long e = blockIdx.x * (long long)blockDim.x + threadIdx.x; e < E; e += stride) {
        int s = idx_at(ei, e);
        int d = idx_at(ei, E + e);
        int pos = rp[d] + atomicAdd(&fill[d], 1);
        csr[pos] = make_float2(__int_as_float(s), dinv[s] * dinv[d]);
    }
}

// ---------------- propagation: out = A^ in (+bias, relu) ----------------
template <int GROUP, int F>
__global__ void prop_kernel(const float* __restrict__ hin, int in_stride,
                            float* __restrict__ hout, int out_stride,
                            const int* __restrict__ rp, const float2* __restrict__ csr,
                            const float* __restrict__ dinv, const float* __restrict__ bias,
                            int do_relu, int N) {
    constexpr int CH = (F + GROUP - 1) / GROUP;
    const int gpw = 32 / GROUP;
    int warp = (int)((blockIdx.x * (long long)blockDim.x + threadIdx.x) >> 5);
    int lane = threadIdx.x & 31;
    int node = warp * gpw + lane / GROUP;
    int l = lane % GROUP;
    if (node >= N) return;
    float acc[CH];
#pragma unroll
    for (int c = 0; c < CH; c++) acc[c] = 0.f;
    int e = rp[node], end = rp[node + 1];
    for (; e + 1 < end; e += 2) {
        float2 a = csr[e], b = csr[e + 1];
        const float* r0 = hin + (size_t)__float_as_int(a.x) * in_stride;
        const float* r1 = hin + (size_t)__float_as_int(b.x) * in_stride;
#pragma unroll
        for (int c = 0; c < CH; c++) {
            int f = c * GROUP + l;
            if (f < F) acc[c] += a.y * __ldg(r0 + f) + b.y * __ldg(r1 + f);
        }
    }
    if (e < end) {
        float2 a = csr[e];
        const float* r0 = hin + (size_t)__float_as_int(a.x) * in_stride;
#pragma unroll
        for (int c = 0; c < CH; c++) {
            int f = c * GROUP + l;
            if (f < F) acc[c] += a.y * __ldg(r0 + f);
        }
    }
    float ds = dinv[node];
    float sw = ds * ds;  // self loop weight
#pragma unroll
    for (int c = 0; c < CH; c++) {
        int f = c * GROUP + l;
        if (f < F) {
            float v = acc[c] + sw * hin[(size_t)node * in_stride + f];
            if (bias) v += bias[f];
            if (do_relu) v = fmaxf(v, 0.f);
            hout[(size_t)node * out_stride + f] = v;
        }
    }
}

// ---------------- fused F=5 propagation + mean-pool accumulation ----------------
// 8-lane groups per node; lanes 0..4 hold features; grid-stride over nodes.
__global__ void prop_pool_kernel(const float* __restrict__ hin,
                                 const int* __restrict__ rp, const float2* __restrict__ csr,
                                 const float* __restrict__ dinv, const float* __restrict__ bias,
                                 const void* batch, float* gsum, int* gcnt, int N) {
    __shared__ float ss[G * 5];
    __shared__ int sc[G];
    for (int i = threadIdx.x; i < G * 5; i += blockDim.x) ss[i] = 0.f;
    for (int i = threadIdx.x; i < G; i += blockDim.x) sc[i] = 0;
    __syncthreads();
    int lane = threadIdx.x & 31;
    int sub = lane >> 3;            // 4 groups per warp
    int l = lane & 7;
    int wib = threadIdx.x >> 5;     // warp in block (8)
    for (int base = blockIdx.x * 32; base < N; base += gridDim.x * 32) {
        int node = base + wib * 4 + sub;
        if (node < N) {
            float acc = 0.f;
            int e = rp[node], end = rp[node + 1];
            for (; e + 1 < end; e += 2) {
                float2 a = csr[e], b = csr[e + 1];
                if (l < 5) {
                    acc += a.y * __ldg(hin + (size_t)__float_as_int(a.x) * 8 + l)
                         + b.y * __ldg(hin + (size_t)__float_as_int(b.x) * 8 + l);
                }
            }
            if (e < end) {
                float2 a = csr[e];
                if (l < 5) acc += a.y * __ldg(hin + (size_t)__float_as_int(a.x) * 8 + l);
            }
            int g = idx_at(batch, node);
            if (l < 5) {
                float ds = dinv[node];
                float v = acc + ds * ds * hin[(size_t)node * 8 + l] + bias[l];
                atomicAdd(&ss[g * 5 + l], v);
            }
            if (l == 0) atomicAdd(&sc[g], 1);
        }
    }
    __syncthreads();
    for (int i = threadIdx.x; i < G * 5; i += blockDim.x) atomicAdd(&gsum[i], ss[i]);
    for (int i = threadIdx.x; i < G; i += blockDim.x) atomicAdd(&gcnt[i], sc[i]);
}

// ---------------- skinny GEMM: Y[M,NOUT] = X[M,K] @ W[K,NW] (+bias, relu) ----------------
template <int K, int NOUT, int TC, int NW>
__global__ void gemm_kernel(const float* __restrict__ X, int xstride,
                            const float* __restrict__ W, const float* __restrict__ bias,
                            float* __restrict__ Y, int ystride, int do_relu, int M) {
    constexpr int TPR = NOUT / TC;
    constexpr int R = 256 / TPR;
    __shared__ float Ws[K * NOUT];
    for (int i = threadIdx.x; i < K * NOUT; i += 256) {
        int k = i / NOUT, c = i % NOUT;
        Ws[i] = (c < NW) ? W[k * NW + c] : 0.f;
    }
    __syncthreads();
    int r = blockIdx.x * R + threadIdx.x / TPR;
    int c0 = (threadIdx.x % TPR) * TC;
    if (r >= M) return;
    float acc[TC];
#pragma unroll
    for (int t = 0; t < TC; t++) acc[t] = 0.f;
    const float* xrow = X + (size_t)r * xstride;
#pragma unroll 4
    for (int k = 0; k < K; k++) {
        float xv = __ldg(xrow + k);
        if (TC % 4 == 0) {
#pragma unroll
            for (int t = 0; t < TC; t += 4) {
                float4 w = *(const float4*)&Ws[k * NOUT + c0 + t];
                acc[t + 0] += xv * w.x;
                acc[t + 1] += xv * w.y;
                acc[t + 2] += xv * w.z;
                acc[t + 3] += xv * w.w;
            }
        } else {
#pragma unroll
            for (int t = 0; t < TC; t++) acc[t] += xv * Ws[k * NOUT + c0 + t];
        }
    }
#pragma unroll
    for (int t = 0; t < TC; t++) {
        int c = c0 + t;
        float v = acc[t];
        if (bias && c < NW) v += bias[c];
        if (do_relu) v = fmaxf(v, 0.f);
        Y[(size_t)r * ystride + c] = v;
    }
}

// ---------------- final FC + log_softmax ----------------
__global__ void final_kernel(const float* __restrict__ Wfc, const float* __restrict__ bfc,
                             float* __restrict__ out) {
    int g = threadIdx.x;
    if (g >= G) return;
    float f[10];
    float co = fmaxf((float)gcnt_o[g], 1.f);
    float cl = fmaxf((float)gcnt_l[g], 1.f);
#pragma unroll
    for (int j = 0; j < 5; j++) {
        f[j] = gsum_o[g * 5 + j] / co;
        f[5 + j] = gsum_l[g * 5 + j] / cl;
    }
    float y0 = bfc[0], y1 = bfc[1];
#pragma unroll
    for (int j = 0; j < 10; j++) {
        y0 += f[j] * Wfc[j * 2 + 0];
        y1 += f[j] * Wfc[j * 2 + 1];
    }
    float m = fmaxf(y0, y1);
    float lse = m + logf(expf(y0 - m) + expf(y1 - m));
    out[g * 2 + 0] = y0 - lse;
    out[g * 2 + 1] = y1 - lse;
}

// ---------------- host side ----------------
struct SymPtrs {
    float2 *csr_o_, *csr_l_;
    int *rp_o_, *rp_l_, *cnt_o_, *cnt_l_, *fill_o_, *fill_l_, *gcnt_o_, *gcnt_l_;
    int *bsum_o_, *bsum_l_;
    float *dinv_o_, *dinv_l_;
    float *P1_, *H1_, *T2_, *H2_, *T3_, *PL_, *HL1_, *TL_;
    float *gsum_o_, *gsum_l_;
    cudaStream_t s1, s2;
    cudaEvent_t evRoot, ev1, ev2;
    bool ready;
};
static SymPtrs SP = {};

static void resolve_syms() {
    if (SP.ready) return;
    cudaGetSymbolAddress((void**)&SP.csr_o_, csr_o);
    cudaGetSymbolAddress((void**)&SP.csr_l_, csr_l);
    cudaGetSymbolAddress((void**)&SP.rp_o_, rp_o);
    cudaGetSymbolAddress((void**)&SP.rp_l_, rp_l);
    cudaGetSymbolAddress((void**)&SP.cnt_o_, cnt_o);
    cudaGetSymbolAddress((void**)&SP.cnt_l_, cnt_l);
    cudaGetSymbolAddress((void**)&SP.fill_o_, fill_o);
    cudaGetSymbolAddress((void**)&SP.fill_l_, fill_l);
    cudaGetSymbolAddress((void**)&SP.gcnt_o_, gcnt_o);
    cudaGetSymbolAddress((void**)&SP.gcnt_l_, gcnt_l);
    cudaGetSymbolAddress((void**)&SP.bsum_o_, bsum_o);
    cudaGetSymbolAddress((void**)&SP.bsum_l_, bsum_l);
    cudaGetSymbolAddress((void**)&SP.dinv_o_, dinv_o);
    cudaGetSymbolAddress((void**)&SP.dinv_l_, dinv_l);
    cudaGetSymbolAddress((void**)&SP.P1_, P1);
    cudaGetSymbolAddress((void**)&SP.H1_, H1b);
    cudaGetSymbolAddress((void**)&SP.T2_, T2b);
    cudaGetSymbolAddress((void**)&SP.H2_, H2b);
    cudaGetSymbolAddress((void**)&SP.T3_, T3b);
    cudaGetSymbolAddress((void**)&SP.PL_, PLb);
    cudaGetSymbolAddress((void**)&SP.HL1_, HL1b);
    cudaGetSymbolAddress((void**)&SP.TL_, TLb);
    cudaGetSymbolAddress((void**)&SP.gsum_o_, gsum_o);
    cudaGetSymbolAddress((void**)&SP.gsum_l_, gsum_l);
    cudaStreamCreateWithFlags(&SP.s1, cudaStreamNonBlocking);
    cudaStreamCreateWithFlags(&SP.s2, cudaStreamNonBlocking);
    cudaEventCreateWithFlags(&SP.evRoot, cudaEventDisableTiming);
    cudaEventCreateWithFlags(&SP.ev1, cudaEventDisableTiming);
    cudaEventCreateWithFlags(&SP.ev2, cudaEventDisableTiming);
    SP.ready = true;
}

extern "C" void kernel_launch(void* const* d_in, const int* in_sizes, int n_in,
                              void* d_out, int out_size) {
    resolve_syms();

    const float* x_o = (const float*)d_in[0];
    const void* ei_o = d_in[1];
    const void* ba_o = d_in[2];
    const float* x_l = (const float*)d_in[3];
    const void* ei_l = d_in[4];
    const void* ba_l = d_in[5];
    const float* W1 = (const float*)d_in[6];
    const float* b1 = (const float*)d_in[7];
    const float* W2 = (const float*)d_in[8];
    const float* b2 = (const float*)d_in[9];
    const float* W5 = (const float*)d_in[10];
    const float* b5 = (const float*)d_in[11];
    const float* W3 = (const float*)d_in[12];
    const float* b3 = (const float*)d_in[13];
    const float* W4 = (const float*)d_in[14];
    const float* b4 = (const float*)d_in[15];
    const float* Wfc = (const float*)d_in[16];
    const float* bfc = (const float*)d_in[17];
    float* out = (float*)d_out;

    int N = in_sizes[0] / 25;
    long long E = (long long)in_sizes[1] / 2;
    int SB = (N + 1023) / 1024;       // scan blocks
    int pb32 = (N * 32 + 255) / 256;  // warp-per-node blocks

    // common prologue on the capture stream
    detect_kernel<<<1, 32>>>((const unsigned*)ei_o);
    init_kernel<<<256, 256>>>(N);

    // fork
    cudaEventRecord(SP.evRoot, 0);
    cudaStreamWaitEvent(SP.s1, SP.evRoot, 0);
    cudaStreamWaitEvent(SP.s2, SP.evRoot, 0);

    // ---- origin branch (s1) ----
    hist_kernel<<<512, 256, 0, SP.s1>>>(ei_o, E, SP.cnt_o_);
    scan1_kernel<<<SB, 1024, 0, SP.s1>>>(SP.cnt_o_, SP.dinv_o_, SP.bsum_o_, N);
    scan2_kernel<<<1, 128, 0, SP.s1>>>(SP.bsum_o_, SP.rp_o_, SB, N);
    scan3_kernel<<<SB, 1024, 0, SP.s1>>>(SP.cnt_o_, SP.bsum_o_, SP.rp_o_, N);
    scatter_kernel<<<512, 256, 0, SP.s1>>>(ei_o, E, SP.rp_o_, SP.fill_o_, SP.dinv_o_, SP.csr_o_);
    prop_kernel<32, 25><<<pb32, 256, 0, SP.s1>>>(x_o, 25, SP.P1_, 32, SP.rp_o_, SP.csr_o_,
                                                 SP.dinv_o_, nullptr, 0, N);
    gemm_kernel<25, 128, 8, 128><<<(N + 15) / 16, 256, 0, SP.s1>>>(SP.P1_, 32, W1, b1, SP.H1_, 128, 1, N);
    gemm_kernel<128, 64, 4, 64><<<(N + 15) / 16, 256, 0, SP.s1>>>(SP.H1_, 128, W2, nullptr, SP.T2_, 64, 0, N);
    prop_kernel<32, 64><<<pb32, 256, 0, SP.s1>>>(SP.T2_, 64, SP.H2_, 64, SP.rp_o_, SP.csr_o_,
                                                 SP.dinv_o_, b2, 1, N);
    gemm_kernel<64, 8, 1, 5><<<(N + 31) / 32, 256, 0, SP.s1>>>(SP.H2_, 64, W5, nullptr, SP.T3_, 8, 0, N);
    prop_pool_kernel<<<512, 256, 0, SP.s1>>>(SP.T3_, SP.rp_o_, SP.csr_o_, SP.dinv_o_, b5,
                                             ba_o, SP.gsum_o_, SP.gcnt_o_, N);

    // ---- line branch (s2) ----
    hist_kernel<<<512, 256, 0, SP.s2>>>(ei_l, E, SP.cnt_l_);
    scan1_kernel<<<SB, 1024, 0, SP.s2>>>(SP.cnt_l_, SP.dinv_l_, SP.bsum_l_, N);
    scan2_kernel<<<1, 128, 0, SP.s2>>>(SP.bsum_l_, SP.rp_l_, SB, N);
    scan3_kernel<<<SB, 1024, 0, SP.s2>>>(SP.cnt_l_, SP.bsum_l_, SP.rp_l_, N);
    scatter_kernel<<<512, 256, 0, SP.s2>>>(ei_l, E, SP.rp_l_, SP.fill_l_, SP.dinv_l_, SP.csr_l_);
    prop_kernel<32, 51><<<pb32, 256, 0, SP.s2>>>(x_l, 51, SP.PL_, 52, SP.rp_l_, SP.csr_l_,
                                                 SP.dinv_l_, nullptr, 0, N);
    gemm_kernel<51, 64, 4, 64><<<(N + 15) / 16, 256, 0, SP.s2>>>(SP.PL_, 52, W3, b3, SP.HL1_, 64, 1, N);
    gemm_kernel<64, 8, 1, 5><<<(N + 31) / 32, 256, 0, SP.s2>>>(SP.HL1_, 64, W4, nullptr, SP.TL_, 8, 0, N);
    prop_pool_kernel<<<512, 256, 0, SP.s2>>>(SP.TL_, SP.rp_l_, SP.csr_l_, SP.dinv_l_, b4,
                                             ba_l, SP.gsum_l_, SP.gcnt_l_, N);

    // join
    cudaEventRecord(SP.ev1, SP.s1);
    cudaEventRecord(SP.ev2, SP.s2);
    cudaStreamWaitEvent(0, SP.ev1, 0);
    cudaStreamWaitEvent(0, SP.ev2, 0);

    final_kernel<<<1, G>>>(Wfc, bfc, out);
}

// round 7
// speedup vs baseline: 1.6431x; 1.1752x over previous
#include <cuda_runtime.h>

#define G 64
#define NCAP 100352
#define ECAP 1605632

// ---------------- device scratch (static; no allocation allowed) ----------------
__device__ int g_idx64;

__device__ int cnt_o[NCAP], cnt_l[NCAP], fill_o[NCAP], fill_l[NCAP];
__device__ int rp_o[NCAP + 1], rp_l[NCAP + 1];
__device__ int bsum_o[256], bsum_l[256];
__device__ float dinv_o[NCAP], dinv_l[NCAP];
__device__ float2 csr_o[ECAP], csr_l[ECAP];

__device__ float XPo[NCAP * 32];         // x_origin padded to stride 32
__device__ float XPl[NCAP * 64];         // x_line padded to stride 64
__device__ float P1[NCAP * 32];          // A^ x_origin (25 used, stride 32)
__device__ float H1b[NCAP * 128];        // relu(P1 W1 + b1)
__device__ float T2b[NCAP * 64];         // H1 W2
__device__ float H2b[NCAP * 64];         // relu(A^ T2 + b2)
__device__ float T3b[NCAP * 8];          // H2 W5 (5 used, stride 8)
__device__ float PLb[NCAP * 64];         // A^ x_line (51 used, stride 64)
__device__ float HL1b[NCAP * 64];        // relu(PL W3 + b3)
__device__ float TLb[NCAP * 8];          // HL1 W4

__device__ float gsum_o[G * 5], gsum_l[G * 5];
__device__ int gcnt_o[G], gcnt_l[G];

// ---------------- index width handling ----------------
__device__ __forceinline__ int idx_at(const void* p, long long i) {
    if (g_idx64) return (int)((const long long*)p)[i];
    return ((const int*)p)[i];
}

__global__ void detect_kernel(const unsigned* p) {
    if (blockIdx.x == 0 && threadIdx.x == 0) {
        int all0 = 1;
        for (int i = 1; i < 128; i += 2) all0 &= (p[i] == 0u);
        g_idx64 = all0;  // high words of nonneg int64 are all zero
    }
}

// ---------------- init (zero per-launch state) ----------------
__global__ void init_kernel(int N) {
    int i = blockIdx.x * blockDim.x + threadIdx.x;
    int stride = gridDim.x * blockDim.x;
    for (int k = i; k < N; k += stride) {
        cnt_o[k] = 0; cnt_l[k] = 0; fill_o[k] = 0; fill_l[k] = 0;
    }
    if (i < G * 5) { gsum_o[i] = 0.f; gsum_l[i] = 0.f; }
    if (i < G)     { gcnt_o[i] = 0;   gcnt_l[i] = 0; }
}

// ---------------- pad copy: x[N,F] -> xp[N,S] (zero pad) ----------------
__global__ void pad_kernel(const float* __restrict__ x, int F,
                           float* __restrict__ xp, int S, long long total) {
    long long i = blockIdx.x * (long long)blockDim.x + threadIdx.x;
    long long stride = (long long)gridDim.x * blockDim.x;
    for (; i < total; i += stride) {
        int node = (int)(i / S), c = (int)(i % S);
        xp[i] = (c < F) ? x[(size_t)node * F + c] : 0.f;
    }
}

// ---------------- CSR build ----------------
__global__ void hist_kernel(const void* ei, long long E, int* cnt) {
    long long stride = (long long)gridDim.x * blockDim.x;
    for (long long e = blockIdx.x * (long long)blockDim.x + threadIdx.x; e < E; e += stride) {
        int d = idx_at(ei, E + e);  // dst = row 1
        atomicAdd(&cnt[d], 1);
    }
}

// scan phase 1: per-1024-block sums (+ fused dinv)
__global__ void scan1_kernel(const int* __restrict__ cnt, float* __restrict__ dinv,
                             int* __restrict__ bsum, int N) {
    __shared__ int wsum[32];
    int tid = threadIdx.x, lane = tid & 31, wid = tid >> 5;
    int i = blockIdx.x * 1024 + tid;
    int v = (i < N) ? cnt[i] : 0;
    if (i < N) dinv[i] = rsqrtf((float)(v + 1));
    int x = v;
#pragma unroll
    for (int o = 16; o > 0; o >>= 1) x += __shfl_down_sync(0xffffffffu, x, o);
    if (lane == 0) wsum[wid] = x;
    __syncthreads();
    if (wid == 0) {
        int s = wsum[lane];
#pragma unroll
        for (int o = 16; o > 0; o >>= 1) s += __shfl_down_sync(0xffffffffu, s, o);
        if (lane == 0) bsum[blockIdx.x] = s;
    }
}

// scan phase 2: exclusive scan of <=128 block sums (in place), set rp[N]
__global__ void scan2_kernel(int* __restrict__ bsum, int* __restrict__ rp, int B, int N) {
    __shared__ int ws[4];
    int tid = threadIdx.x, lane = tid & 31, wid = tid >> 5;
    int v = (tid < B) ? bsum[tid] : 0;
    int x = v;
#pragma unroll
    for (int o = 1; o < 32; o <<= 1) {
        int y = __shfl_up_sync(0xffffffffu, x, o);
        if (lane >= o) x += y;
    }
    if (lane == 31) ws[wid] = x;
    __syncthreads();
    int add = 0;
    for (int w = 0; w < wid; w++) add += ws[w];
    x += add;
    if (tid < B) bsum[tid] = x - v;   // exclusive
    if (tid == B - 1) rp[N] = x;      // total
}

// scan phase 3: local exclusive scan + block offset
__global__ void scan3_kernel(const int* __restrict__ cnt, const int* __restrict__ boff,
                             int* __restrict__ rp, int N) {
    __shared__ int wsum[32];
    int tid = threadIdx.x, lane = tid & 31, wid = tid >> 5;
    int i = blockIdx.x * 1024 + tid;
    int v = (i < N) ? cnt[i] : 0;
    int x = v;
#pragma unroll
    for (int o = 1; o < 32; o <<= 1) {
        int y = __shfl_up_sync(0xffffffffu, x, o);
        if (lane >= o) x += y;
    }
    if (lane == 31) wsum[wid] = x;
    __syncthreads();
    if (wid == 0) {
        int s = wsum[lane];
#pragma unroll
        for (int o = 1; o < 32; o <<= 1) {
            int y = __shfl_up_sync(0xffffffffu, s, o);
            if (lane >= o) s += y;
        }
        wsum[lane] = s;
    }
    __syncthreads();
    int off = boff[blockIdx.x] + (wid > 0 ? wsum[wid - 1] : 0);
    if (i < N) rp[i] = off + x - v;
}

__global__ void scatter_kernel(const void* ei, long long E, const int* __restrict__ rp,
                               int* fill, const float* __restrict__ dinv, float2* csr) {
    long long stride = (long long)gridDim.x * blockDim.x;
    for (long long e = blockIdx.x * (long long)blockDim.x + threadIdx.x; e < E; e += stride) {
        int s = idx_at(ei, e);
        int d = idx_at(ei, E + e);
        int pos = rp[d] + atomicAdd(&fill[d], 1);
        csr[pos] = make_float2(__int_as_float(s), dinv[s] * dinv[d]);
    }
}

// ---------------- vectorized propagation: out = A^ in (+bias, relu) ----------------
// GROUP lanes per node; lane l covers feature floats [4l, 4l+4). Strides = 4*GROUP.
template <int GROUP>
__global__ void prop4_kernel(const float* __restrict__ hin, float* __restrict__ hout,
                             const int* __restrict__ rp, const float2* __restrict__ csr,
                             const float* __restrict__ dinv, const float* __restrict__ bias,
                             int do_relu, int N) {
    constexpr int S = 4 * GROUP;
    const int gpw = 32 / GROUP;
    int warp = (int)((blockIdx.x * (long long)blockDim.x + threadIdx.x) >> 5);
    int lane = threadIdx.x & 31;
    int node = warp * gpw + lane / GROUP;
    int l = lane % GROUP;
    if (node >= N) return;
    float ax = 0.f, ay = 0.f, az = 0.f, aw = 0.f;
    int e = rp[node], end = rp[node + 1];
    for (; e + 1 < end; e += 2) {
        float2 a = csr[e], b = csr[e + 1];
        float4 va = __ldg((const float4*)(hin + (size_t)__float_as_int(a.x) * S) + l);
        float4 vb = __ldg((const float4*)(hin + (size_t)__float_as_int(b.x) * S) + l);
        ax += a.y * va.x + b.y * vb.x;
        ay += a.y * va.y + b.y * vb.y;
        az += a.y * va.z + b.y * vb.z;
        aw += a.y * va.w + b.y * vb.w;
    }
    if (e < end) {
        float2 a = csr[e];
        float4 va = __ldg((const float4*)(hin + (size_t)__float_as_int(a.x) * S) + l);
        ax += a.y * va.x; ay += a.y * va.y; az += a.y * va.z; aw += a.y * va.w;
    }
    float ds = dinv[node];
    float sw = ds * ds;  // self loop weight
    float4 sv = __ldg((const float4*)(hin + (size_t)node * S) + l);
    ax += sw * sv.x; ay += sw * sv.y; az += sw * sv.z; aw += sw * sv.w;
    if (bias) {
        float4 bv = *((const float4*)bias + l);
        ax += bv.x; ay += bv.y; az += bv.z; aw += bv.w;
    }
    if (do_relu) {
        ax = fmaxf(ax, 0.f); ay = fmaxf(ay, 0.f); az = fmaxf(az, 0.f); aw = fmaxf(aw, 0.f);
    }
    *((float4*)(hout + (size_t)node * S) + l) = make_float4(ax, ay, az, aw);
}

// ---------------- fused F=5 propagation + mean-pool (one thread per node) ----------------
__global__ void prop_pool_kernel(const float* __restrict__ hin,
                                 const int* __restrict__ rp, const float2* __restrict__ csr,
                                 const float* __restrict__ dinv, const float* __restrict__ bias,
                                 const void* batch, float* gsum, int* gcnt, int N) {
    __shared__ float ss[G * 5];
    __shared__ int sc[G];
    for (int i = threadIdx.x; i < G * 5; i += blockDim.x) ss[i] = 0.f;
    for (int i = threadIdx.x; i < G; i += blockDim.x) sc[i] = 0;
    __syncthreads();
    float bb0 = bias[0], bb1 = bias[1], bb2 = bias[2], bb3 = bias[3], bb4 = bias[4];
    int stride = gridDim.x * blockDim.x;
    for (int node = blockIdx.x * blockDim.x + threadIdx.x; node < N; node += stride) {
        float a0 = 0.f, a1 = 0.f, a2 = 0.f, a3 = 0.f, a4 = 0.f;
        int e = rp[node], end = rp[node + 1];
        for (; e + 1 < end; e += 2) {
            float2 wa = csr[e], wb = csr[e + 1];
            const float* ra = hin + (size_t)__float_as_int(wa.x) * 8;
            const float* rb = hin + (size_t)__float_as_int(wb.x) * 8;
            float4 va = __ldg((const float4*)ra);
            float s4a = __ldg(ra + 4);
            float4 vb = __ldg((const float4*)rb);
            float s4b = __ldg(rb + 4);
            a0 += wa.y * va.x + wb.y * vb.x;
            a1 += wa.y * va.y + wb.y * vb.y;
            a2 += wa.y * va.z + wb.y * vb.z;
            a3 += wa.y * va.w + wb.y * vb.w;
            a4 += wa.y * s4a + wb.y * s4b;
        }
        if (e < end) {
            float2 wa = csr[e];
            const float* ra = hin + (size_t)__float_as_int(wa.x) * 8;
            float4 va = __ldg((const float4*)ra);
            float s4a = __ldg(ra + 4);
            a0 += wa.y * va.x; a1 += wa.y * va.y; a2 += wa.y * va.z;
            a3 += wa.y * va.w; a4 += wa.y * s4a;
        }
        float ds = dinv[node];
        float sw = ds * ds;
        const float* rs = hin + (size_t)node * 8;
        float4 vs = *(const float4*)rs;
        float s4s = rs[4];
        a0 += sw * vs.x + bb0; a1 += sw * vs.y + bb1; a2 += sw * vs.z + bb2;
        a3 += sw * vs.w + bb3; a4 += sw * s4s + bb4;
        int g = idx_at(batch, node);
        atomicAdd(&ss[g * 5 + 0], a0);
        atomicAdd(&ss[g * 5 + 1], a1);
        atomicAdd(&ss[g * 5 + 2], a2);
        atomicAdd(&ss[g * 5 + 3], a3);
        atomicAdd(&ss[g * 5 + 4], a4);
        atomicAdd(&sc[g], 1);
    }
    __syncthreads();
    for (int i = threadIdx.x; i < G * 5; i += blockDim.x) atomicAdd(&gsum[i], ss[i]);
    for (int i = threadIdx.x; i < G; i += blockDim.x) atomicAdd(&gcnt[i], sc[i]);
}

// ---------------- row-tiled skinny GEMM: Y[M,NOUT] = X[M,K] @ W[K,NW] ----------------
template <int K, int NOUT, int TC, int RM, int NW>
__global__ void gemm_rm_kernel(const float* __restrict__ X, int xstride,
                               const float* __restrict__ W, const float* __restrict__ bias,
                               float* __restrict__ Y, int ystride, int do_relu, int M) {
    constexpr int TPR = NOUT / TC;      // threads covering one row's columns
    constexpr int RT = 256 / TPR;       // row-thread groups per block
    constexpr int R = RT * RM;          // rows per block
    __shared__ float Ws[K * NOUT];
    for (int i = threadIdx.x; i < K * NOUT; i += 256) {
        int k = i / NOUT, c = i % NOUT;
        Ws[i] = (c < NW) ? W[k * NW + c] : 0.f;
    }
    __syncthreads();
    int rt = threadIdx.x / TPR;
    int c0 = (threadIdx.x % TPR) * TC;
    int r0 = blockIdx.x * R + rt * RM;
    if (r0 >= M) return;
    float acc[RM][TC];
#pragma unroll
    for (int m = 0; m < RM; m++)
#pragma unroll
        for (int t = 0; t < TC; t++) acc[m][t] = 0.f;
#pragma unroll 2
    for (int k = 0; k < K; k++) {
        float xv[RM];
#pragma unroll
        for (int m = 0; m < RM; m++) {
            int r = r0 + m;
            if (r >= M) r = M - 1;
            xv[m] = __ldg(X + (size_t)r * xstride + k);
        }
#pragma unroll
        for (int t = 0; t < TC; t += 4) {
            float4 w = *(const float4*)&Ws[k * NOUT + c0 + t];
#pragma unroll
            for (int m = 0; m < RM; m++) {
                acc[m][t + 0] += xv[m] * w.x;
                acc[m][t + 1] += xv[m] * w.y;
                acc[m][t + 2] += xv[m] * w.z;
                acc[m][t + 3] += xv[m] * w.w;
            }
        }
    }
#pragma unroll
    for (int m = 0; m < RM; m++) {
        int r = r0 + m;
        if (r >= M) break;
#pragma unroll
        for (int t = 0; t < TC; t++) {
            int c = c0 + t;
            float v = acc[m][t];
            if (c < NW) {
                if (bias) v += bias[c];
                if (do_relu) v = fmaxf(v, 0.f);
            }
            Y[(size_t)r * ystride + c] = v;
        }
    }
}

// ---------------- small GEMM (64 -> 5, stride-8 out) ----------------
template <int K, int NOUT, int TC, int NW>
__global__ void gemm_kernel(const float* __restrict__ X, int xstride,
                            const float* __restrict__ W, const float* __restrict__ bias,
                            float* __restrict__ Y, int ystride, int do_relu, int M) {
    constexpr int TPR = NOUT / TC;
    constexpr int R = 256 / TPR;
    __shared__ float Ws[K * NOUT];
    for (int i = threadIdx.x; i < K * NOUT; i += 256) {
        int k = i / NOUT, c = i % NOUT;
        Ws[i] = (c < NW) ? W[k * NW + c] : 0.f;
    }
    __syncthreads();
    int r = blockIdx.x * R + threadIdx.x / TPR;
    int c0 = (threadIdx.x % TPR) * TC;
    if (r >= M) return;
    float acc[TC];
#pragma unroll
    for (int t = 0; t < TC; t++) acc[t] = 0.f;
    const float* xrow = X + (size_t)r * xstride;
#pragma unroll 4
    for (int k = 0; k < K; k++) {
        float xv = __ldg(xrow + k);
#pragma unroll
        for (int t = 0; t < TC; t++) acc[t] += xv * Ws[k * NOUT + c0 + t];
    }
#pragma unroll
    for (int t = 0; t < TC; t++) {
        int c = c0 + t;
        float v = acc[t];
        if (bias && c < NW) v += bias[c];
        if (do_relu) v = fmaxf(v, 0.f);
        Y[(size_t)r * ystride + c] = v;
    }
}

// ---------------- final FC + log_softmax ----------------
__global__ void final_kernel(const float* __restrict__ Wfc, const float* __restrict__ bfc,
                             float* __restrict__ out) {
    int g = threadIdx.x;
    if (g >= G) return;
    float f[10];
    float co = fmaxf((float)gcnt_o[g], 1.f);
    float cl = fmaxf((float)gcnt_l[g], 1.f);
#pragma unroll
    for (int j = 0; j < 5; j++) {
        f[j] = gsum_o[g * 5 + j] / co;
        f[5 + j] = gsum_l[g * 5 + j] / cl;
    }
    float y0 = bfc[0], y1 = bfc[1];
#pragma unroll
    for (int j = 0; j < 10; j++) {
        y0 += f[j] * Wfc[j * 2 + 0];
        y1 += f[j] * Wfc[j * 2 + 1];
    }
    float m = fmaxf(y0, y1);
    float lse = m + logf(expf(y0 - m) + expf(y1 - m));
    out[g * 2 + 0] = y0 - lse;
    out[g * 2 + 1] = y1 - lse;
}

// ---------------- host side ----------------
struct SymPtrs {
    float2 *csr_o_, *csr_l_;
    int *rp_o_, *rp_l_, *cnt_o_, *cnt_l_, *fill_o_, *fill_l_, *gcnt_o_, *gcnt_l_;
    int *bsum_o_, *bsum_l_;
    float *dinv_o_, *dinv_l_;
    float *XPo_, *XPl_, *P1_, *H1_, *T2_, *H2_, *T3_, *PL_, *HL1_, *TL_;
    float *gsum_o_, *gsum_l_;
    cudaStream_t s1, s2;
    cudaEvent_t evRoot, ev1, ev2;
    bool ready;
};
static SymPtrs SP = {};

static void resolve_syms() {
    if (SP.ready) return;
    cudaGetSymbolAddress((void**)&SP.csr_o_, csr_o);
    cudaGetSymbolAddress((void**)&SP.csr_l_, csr_l);
    cudaGetSymbolAddress((void**)&SP.rp_o_, rp_o);
    cudaGetSymbolAddress((void**)&SP.rp_l_, rp_l);
    cudaGetSymbolAddress((void**)&SP.cnt_o_, cnt_o);
    cudaGetSymbolAddress((void**)&SP.cnt_l_, cnt_l);
    cudaGetSymbolAddress((void**)&SP.fill_o_, fill_o);
    cudaGetSymbolAddress((void**)&SP.fill_l_, fill_l);
    cudaGetSymbolAddress((void**)&SP.gcnt_o_, gcnt_o);
    cudaGetSymbolAddress((void**)&SP.gcnt_l_, gcnt_l);
    cudaGetSymbolAddress((void**)&SP.bsum_o_, bsum_o);
    cudaGetSymbolAddress((void**)&SP.bsum_l_, bsum_l);
    cudaGetSymbolAddress((void**)&SP.dinv_o_, dinv_o);
    cudaGetSymbolAddress((void**)&SP.dinv_l_, dinv_l);
    cudaGetSymbolAddress((void**)&SP.XPo_, XPo);
    cudaGetSymbolAddress((void**)&SP.XPl_, XPl);
    cudaGetSymbolAddress((void**)&SP.P1_, P1);
    cudaGetSymbolAddress((void**)&SP.H1_, H1b);
    cudaGetSymbolAddress((void**)&SP.T2_, T2b);
    cudaGetSymbolAddress((void**)&SP.H2_, H2b);
    cudaGetSymbolAddress((void**)&SP.T3_, T3b);
    cudaGetSymbolAddress((void**)&SP.PL_, PLb);
    cudaGetSymbolAddress((void**)&SP.HL1_, HL1b);
    cudaGetSymbolAddress((void**)&SP.TL_, TLb);
    cudaGetSymbolAddress((void**)&SP.gsum_o_, gsum_o);
    cudaGetSymbolAddress((void**)&SP.gsum_l_, gsum_l);
    cudaStreamCreateWithFlags(&SP.s1, cudaStreamNonBlocking);
    cudaStreamCreateWithFlags(&SP.s2, cudaStreamNonBlocking);
    cudaEventCreateWithFlags(&SP.evRoot, cudaEventDisableTiming);
    cudaEventCreateWithFlags(&SP.ev1, cudaEventDisableTiming);
    cudaEventCreateWithFlags(&SP.ev2, cudaEventDisableTiming);
    SP.ready = true;
}

extern "C" void kernel_launch(void* const* d_in, const int* in_sizes, int n_in,
                              void* d_out, int out_size) {
    resolve_syms();

    const float* x_o = (const float*)d_in[0];
    const void* ei_o = d_in[1];
    const void* ba_o = d_in[2];
    const float* x_l = (const float*)d_in[3];
    const void* ei_l = d_in[4];
    const void* ba_l = d_in[5];
    const float* W1 = (const float*)d_in[6];
    const float* b1 = (const float*)d_in[7];
    const float* W2 = (const float*)d_in[8];
    const float* b2 = (const float*)d_in[9];
    const float* W5 = (const float*)d_in[10];
    const float* b5 = (const float*)d_in[11];
    const float* W3 = (const float*)d_in[12];
    const float* b3 = (const float*)d_in[13];
    const float* W4 = (const float*)d_in[14];
    const float* b4 = (const float*)d_in[15];
    const float* Wfc = (const float*)d_in[16];
    const float* bfc = (const float*)d_in[17];
    float* out = (float*)d_out;

    int N = in_sizes[0] / 25;
    long long E = (long long)in_sizes[1] / 2;
    int SB = (N + 1023) / 1024;        // scan blocks
    int pb16 = (N * 16 + 255) / 256;   // GROUP=16 prop blocks (2 nodes/warp)
    int pb8v = (N * 8 + 255) / 256;    // GROUP=8 prop blocks (4 nodes/warp)

    // common prologue on the capture stream
    detect_kernel<<<1, 32>>>((const unsigned*)ei_o);
    init_kernel<<<256, 256>>>(N);

    // fork
    cudaEventRecord(SP.evRoot, 0);
    cudaStreamWaitEvent(SP.s1, SP.evRoot, 0);
    cudaStreamWaitEvent(SP.s2, SP.evRoot, 0);

    // ---- origin branch (s1) ----
    pad_kernel<<<2048, 256, 0, SP.s1>>>(x_o, 25, SP.XPo_, 32, (long long)N * 32);
    hist_kernel<<<512, 256, 0, SP.s1>>>(ei_o, E, SP.cnt_o_);
    scan1_kernel<<<SB, 1024, 0, SP.s1>>>(SP.cnt_o_, SP.dinv_o_, SP.bsum_o_, N);
    scan2_kernel<<<1, 128, 0, SP.s1>>>(SP.bsum_o_, SP.rp_o_, SB, N);
    scan3_kernel<<<SB, 1024, 0, SP.s1>>>(SP.cnt_o_, SP.bsum_o_, SP.rp_o_, N);
    scatter_kernel<<<512, 256, 0, SP.s1>>>(ei_o, E, SP.rp_o_, SP.fill_o_, SP.dinv_o_, SP.csr_o_);
    prop4_kernel<8><<<pb8v, 256, 0, SP.s1>>>(SP.XPo_, SP.P1_, SP.rp_o_, SP.csr_o_,
                                             SP.dinv_o_, nullptr, 0, N);
    gemm_rm_kernel<25, 128, 8, 4, 128><<<(N + 63) / 64, 256, 0, SP.s1>>>(
        SP.P1_, 32, W1, b1, SP.H1_, 128, 1, N);
    gemm_rm_kernel<128, 64, 8, 4, 64><<<(N + 127) / 128, 256, 0, SP.s1>>>(
        SP.H1_, 128, W2, nullptr, SP.T2_, 64, 0, N);
    prop4_kernel<16><<<pb16, 256, 0, SP.s1>>>(SP.T2_, SP.H2_, SP.rp_o_, SP.csr_o_,
                                              SP.dinv_o_, b2, 1, N);
    gemm_kernel<64, 8, 1, 5><<<(N + 31) / 32, 256, 0, SP.s1>>>(
        SP.H2_, 64, W5, nullptr, SP.T3_, 8, 0, N);
    prop_pool_kernel<<<512, 256, 0, SP.s1>>>(SP.T3_, SP.rp_o_, SP.csr_o_, SP.dinv_o_, b5,
                                             ba_o, SP.gsum_o_, SP.gcnt_o_, N);

    // ---- line branch (s2) ----
    pad_kernel<<<2048, 256, 0, SP.s2>>>(x_l, 51, SP.XPl_, 64, (long long)N * 64);
    hist_kernel<<<512, 256, 0, SP.s2>>>(ei_l, E, SP.cnt_l_);
    scan1_kernel<<<SB, 1024, 0, SP.s2>>>(SP.cnt_l_, SP.dinv_l_, SP.bsum_l_, N);
    scan2_kernel<<<1, 128, 0, SP.s2>>>(SP.bsum_l_, SP.rp_l_, SB, N);
    scan3_kernel<<<SB, 1024, 0, SP.s2>>>(SP.cnt_l_, SP.bsum_l_, SP.rp_l_, N);
    scatter_kernel<<<512, 256, 0, SP.s2>>>(ei_l, E, SP.rp_l_, SP.fill_l_, SP.dinv_l_, SP.csr_l_);
    prop4_kernel<16><<<pb16, 256, 0, SP.s2>>>(SP.XPl_, SP.PL_, SP.rp_l_, SP.csr_l_,
                                              SP.dinv_l_, nullptr, 0, N);
    gemm_rm_kernel<51, 64, 8, 4, 64><<<(N + 127) / 128, 256, 0, SP.s2>>>(
        SP.PL_, 64, W3, b3, SP.HL1_, 64, 1, N);
    gemm_kernel<64, 8, 1, 5><<<(N + 31) / 32, 256, 0, SP.s2>>>(
        SP.HL1_, 64, W4, nullptr, SP.TL_, 8, 0, N);
    prop_pool_kernel<<<512, 256, 0, SP.s2>>>(SP.TL_, SP.rp_l_, SP.csr_l_, SP.dinv_l_, b4,
                                             ba_l, SP.gsum_l_, SP.gcnt_l_, N);

    // join
    cudaEventRecord(SP.ev1, SP.s1);
    cudaEventRecord(SP.ev2, SP.s2);
    cudaStreamWaitEvent(0, SP.ev1, 0);
    cudaStreamWaitEvent(0, SP.ev2, 0);

    final_kernel<<<1, G>>>(Wfc, bfc, out);
}

// round 8
// speedup vs baseline: 1.6948x; 1.0315x over previous
#include <cuda_runtime.h>

#define G 64
#define NCAP 100352
#define ECAP 1605632

// ---------------- device scratch (static; no allocation allowed) ----------------
__device__ int g_idx64;

__device__ int cnt_o[NCAP], cnt_l[NCAP], fill_o[NCAP], fill_l[NCAP];
__device__ int rp_o[NCAP + 1], rp_l[NCAP + 1];
__device__ int bsum_o[256], bsum_l[256];
__device__ float dinv_o[NCAP], dinv_l[NCAP];
__device__ float2 csr_o[ECAP], csr_l[ECAP];

__device__ float XPo[NCAP * 32];         // x_origin padded to stride 32
__device__ float XPl[NCAP * 64];         // x_line padded to stride 64
__device__ float P1[NCAP * 32];          // A^ x_origin (25 used, stride 32)
__device__ float H1b[NCAP * 128];        // relu(P1 W1 + b1)
__device__ float T2b[NCAP * 64];         // H1 W2
__device__ float H2b[NCAP * 64];         // relu(A^ T2 + b2)
__device__ float T3b[NCAP * 8];          // H2 W5 (5 used, stride 8)
__device__ float PLb[NCAP * 64];         // A^ x_line (51 used, stride 64)
__device__ float HL1b[NCAP * 64];        // relu(PL W3 + b3)
__device__ float TLb[NCAP * 8];          // HL1 W4

__device__ float gsum_o[G * 5], gsum_l[G * 5];
__device__ int gcnt_o[G], gcnt_l[G];

// ---------------- index width handling ----------------
__device__ __forceinline__ int idx_at(const void* p, long long i) {
    if (g_idx64) return (int)((const long long*)p)[i];
    return ((const int*)p)[i];
}

__global__ void detect_kernel(const unsigned* p) {
    if (blockIdx.x == 0 && threadIdx.x == 0) {
        int all0 = 1;
        for (int i = 1; i < 128; i += 2) all0 &= (p[i] == 0u);
        g_idx64 = all0;  // high words of nonneg int64 are all zero
    }
}

// ---------------- init (zero per-launch state) ----------------
__global__ void init_kernel(int N) {
    int i = blockIdx.x * blockDim.x + threadIdx.x;
    int stride = gridDim.x * blockDim.x;
    for (int k = i; k < N; k += stride) {
        cnt_o[k] = 0; cnt_l[k] = 0; fill_o[k] = 0; fill_l[k] = 0;
    }
    if (i < G * 5) { gsum_o[i] = 0.f; gsum_l[i] = 0.f; }
    if (i < G)     { gcnt_o[i] = 0;   gcnt_l[i] = 0; }
}

// ---------------- pad copy: x[N,F] -> xp[N,S] (zero pad) ----------------
__global__ void pad_kernel(const float* __restrict__ x, int F,
                           float* __restrict__ xp, int S, long long total) {
    long long i = blockIdx.x * (long long)blockDim.x + threadIdx.x;
    long long stride = (long long)gridDim.x * blockDim.x;
    for (; i < total; i += stride) {
        int node = (int)(i / S), c = (int)(i % S);
        xp[i] = (c < F) ? x[(size_t)node * F + c] : 0.f;
    }
}

// ---------------- CSR build ----------------
__global__ void hist_kernel(const void* ei, long long E, int* cnt) {
    long long stride = (long long)gridDim.x * blockDim.x;
    for (long long e = blockIdx.x * (long long)blockDim.x + threadIdx.x; e < E; e += stride) {
        int d = idx_at(ei, E + e);  // dst = row 1
        atomicAdd(&cnt[d], 1);
    }
}

// scan phase 1: per-1024-block sums (+ fused dinv)
__global__ void scan1_kernel(const int* __restrict__ cnt, float* __restrict__ dinv,
                             int* __restrict__ bsum, int N) {
    __shared__ int wsum[32];
    int tid = threadIdx.x, lane = tid & 31, wid = tid >> 5;
    int i = blockIdx.x * 1024 + tid;
    int v = (i < N) ? cnt[i] : 0;
    if (i < N) dinv[i] = rsqrtf((float)(v + 1));
    int x = v;
#pragma unroll
    for (int o = 16; o > 0; o >>= 1) x += __shfl_down_sync(0xffffffffu, x, o);
    if (lane == 0) wsum[wid] = x;
    __syncthreads();
    if (wid == 0) {
        int s = wsum[lane];
#pragma unroll
        for (int o = 16; o > 0; o >>= 1) s += __shfl_down_sync(0xffffffffu, s, o);
        if (lane == 0) bsum[blockIdx.x] = s;
    }
}

// scan phase 2: exclusive scan of <=128 block sums (in place), set rp[N]
__global__ void scan2_kernel(int* __restrict__ bsum, int* __restrict__ rp, int B, int N) {
    __shared__ int ws[4];
    int tid = threadIdx.x, lane = tid & 31, wid = tid >> 5;
    int v = (tid < B) ? bsum[tid] : 0;
    int x = v;
#pragma unroll
    for (int o = 1; o < 32; o <<= 1) {
        int y = __shfl_up_sync(0xffffffffu, x, o);
        if (lane >= o) x += y;
    }
    if (lane == 31) ws[wid] = x;
    __syncthreads();
    int add = 0;
    for (int w = 0; w < wid; w++) add += ws[w];
    x += add;
    if (tid < B) bsum[tid] = x - v;   // exclusive
    if (tid == B - 1) rp[N] = x;      // total
}

// scan phase 3: local exclusive scan + block offset
__global__ void scan3_kernel(const int* __restrict__ cnt, const int* __restrict__ boff,
                             int* __restrict__ rp, int N) {
    __shared__ int wsum[32];
    int tid = threadIdx.x, lane = tid & 31, wid = tid >> 5;
    int i = blockIdx.x * 1024 + tid;
    int v = (i < N) ? cnt[i] : 0;
    int x = v;
#pragma unroll
    for (int o = 1; o < 32; o <<= 1) {
        int y = __shfl_up_sync(0xffffffffu, x, o);
        if (lane >= o) x += y;
    }
    if (lane == 31) wsum[wid] = x;
    __syncthreads();
    if (wid == 0) {
        int s = wsum[lane];
#pragma unroll
        for (int o = 1; o < 32; o <<= 1) {
            int y = __shfl_up_sync(0xffffffffu, s, o);
            if (lane >= o) s += y;
        }
        wsum[lane] = s;
    }
    __syncthreads();
    int off = boff[blockIdx.x] + (wid > 0 ? wsum[wid - 1] : 0);
    if (i < N) rp[i] = off + x - v;
}

__global__ void scatter_kernel(const void* ei, long long E, const int* __restrict__ rp,
                               int* fill, const float* __restrict__ dinv, float2* csr) {
    long long stride = (long long)gridDim.x * blockDim.x;
    for (long long e = blockIdx.x * (long long)blockDim.x + threadIdx.x; e < E; e += stride) {
        int s = idx_at(ei, e);
        int d = idx_at(ei, E + e);
        int pos = rp[d] + atomicAdd(&fill[d], 1);
        csr[pos] = make_float2(__int_as_float(s), dinv[s] * dinv[d]);
    }
}

// ---------------- vectorized propagation: out = A^ in (+bias, relu) ----------------
// GROUP lanes per node; lane l covers feature floats [4l, 4l+4). Strides = 4*GROUP.
// 4-edge unroll: 4 independent gathers in flight per thread (MLP ~4-5).
template <int GROUP>
__global__ void __launch_bounds__(256) prop4_kernel(
        const float* __restrict__ hin, float* __restrict__ hout,
        const int* __restrict__ rp, const float2* __restrict__ csr,
        const float* __restrict__ dinv, const float* __restrict__ bias,
        int do_relu, int N) {
    constexpr int S = 4 * GROUP;
    const int gpw = 32 / GROUP;
    int warp = (int)((blockIdx.x * (long long)blockDim.x + threadIdx.x) >> 5);
    int lane = threadIdx.x & 31;
    int node = warp * gpw + lane / GROUP;
    int l = lane % GROUP;
    if (node >= N) return;
    float ax = 0.f, ay = 0.f, az = 0.f, aw = 0.f;
    int e = rp[node], end = rp[node + 1];
    for (; e + 3 < end; e += 4) {
        float2 w0 = csr[e], w1 = csr[e + 1], w2 = csr[e + 2], w3 = csr[e + 3];
        float4 v0 = __ldg((const float4*)(hin + (size_t)__float_as_int(w0.x) * S) + l);
        float4 v1 = __ldg((const float4*)(hin + (size_t)__float_as_int(w1.x) * S) + l);
        float4 v2 = __ldg((const float4*)(hin + (size_t)__float_as_int(w2.x) * S) + l);
        float4 v3 = __ldg((const float4*)(hin + (size_t)__float_as_int(w3.x) * S) + l);
        ax += w0.y * v0.x + w1.y * v1.x + w2.y * v2.x + w3.y * v3.x;
        ay += w0.y * v0.y + w1.y * v1.y + w2.y * v2.y + w3.y * v3.y;
        az += w0.y * v0.z + w1.y * v1.z + w2.y * v2.z + w3.y * v3.z;
        aw += w0.y * v0.w + w1.y * v1.w + w2.y * v2.w + w3.y * v3.w;
    }
    for (; e < end; e++) {
        float2 a = csr[e];
        float4 va = __ldg((const float4*)(hin + (size_t)__float_as_int(a.x) * S) + l);
        ax += a.y * va.x; ay += a.y * va.y; az += a.y * va.z; aw += a.y * va.w;
    }
    float ds = dinv[node];
    float sw = ds * ds;  // self loop weight
    float4 sv = __ldg((const float4*)(hin + (size_t)node * S) + l);
    ax += sw * sv.x; ay += sw * sv.y; az += sw * sv.z; aw += sw * sv.w;
    if (bias) {
        float4 bv = *((const float4*)bias + l);
        ax += bv.x; ay += bv.y; az += bv.z; aw += bv.w;
    }
    if (do_relu) {
        ax = fmaxf(ax, 0.f); ay = fmaxf(ay, 0.f); az = fmaxf(az, 0.f); aw = fmaxf(aw, 0.f);
    }
    *((float4*)(hout + (size_t)node * S) + l) = make_float4(ax, ay, az, aw);
}

// ---------------- fused F=5 propagation + mean-pool (one thread per node) ----------------
__global__ void __launch_bounds__(256) prop_pool_kernel(
        const float* __restrict__ hin,
        const int* __restrict__ rp, const float2* __restrict__ csr,
        const float* __restrict__ dinv, const float* __restrict__ bias,
        const void* batch, float* gsum, int* gcnt, int N) {
    __shared__ float ss[G * 5];
    __shared__ int sc[G];
    for (int i = threadIdx.x; i < G * 5; i += blockDim.x) ss[i] = 0.f;
    for (int i = threadIdx.x; i < G; i += blockDim.x) sc[i] = 0;
    __syncthreads();
    float bb0 = bias[0], bb1 = bias[1], bb2 = bias[2], bb3 = bias[3], bb4 = bias[4];
    int stride = gridDim.x * blockDim.x;
    for (int node = blockIdx.x * blockDim.x + threadIdx.x; node < N; node += stride) {
        float a0 = 0.f, a1 = 0.f, a2 = 0.f, a3 = 0.f, a4 = 0.f;
        int e = rp[node], end = rp[node + 1];
        for (; e + 3 < end; e += 4) {
            float2 w0 = csr[e], w1 = csr[e + 1], w2 = csr[e + 2], w3 = csr[e + 3];
            const float* r0 = hin + (size_t)__float_as_int(w0.x) * 8;
            const float* r1 = hin + (size_t)__float_as_int(w1.x) * 8;
            const float* r2 = hin + (size_t)__float_as_int(w2.x) * 8;
            const float* r3 = hin + (size_t)__float_as_int(w3.x) * 8;
            float4 v0 = __ldg((const float4*)r0);
            float4 v1 = __ldg((const float4*)r1);
            float4 v2 = __ldg((const float4*)r2);
            float4 v3 = __ldg((const float4*)r3);
            float s0 = __ldg(r0 + 4), s1 = __ldg(r1 + 4), s2 = __ldg(r2 + 4), s3 = __ldg(r3 + 4);
            a0 += w0.y * v0.x + w1.y * v1.x + w2.y * v2.x + w3.y * v3.x;
            a1 += w0.y * v0.y + w1.y * v1.y + w2.y * v2.y + w3.y * v3.y;
            a2 += w0.y * v0.z + w1.y * v1.z + w2.y * v2.z + w3.y * v3.z;
            a3 += w0.y * v0.w + w1.y * v1.w + w2.y * v2.w + w3.y * v3.w;
            a4 += w0.y * s0 + w1.y * s1 + w2.y * s2 + w3.y * s3;
        }
        for (; e < end; e++) {
            float2 wa = csr[e];
            const float* ra = hin + (size_t)__float_as_int(wa.x) * 8;
            float4 va = __ldg((const float4*)ra);
            float s4a = __ldg(ra + 4);
            a0 += wa.y * va.x; a1 += wa.y * va.y; a2 += wa.y * va.z;
            a3 += wa.y * va.w; a4 += wa.y * s4a;
        }
        float ds = dinv[node];
        float sw = ds * ds;
        const float* rs = hin + (size_t)node * 8;
        float4 vs = *(const float4*)rs;
        float s4s = rs[4];
        a0 += sw * vs.x + bb0; a1 += sw * vs.y + bb1; a2 += sw * vs.z + bb2;
        a3 += sw * vs.w + bb3; a4 += sw * s4s + bb4;
        int g = idx_at(batch, node);
        atomicAdd(&ss[g * 5 + 0], a0);
        atomicAdd(&ss[g * 5 + 1], a1);
        atomicAdd(&ss[g * 5 + 2], a2);
        atomicAdd(&ss[g * 5 + 3], a3);
        atomicAdd(&ss[g * 5 + 4], a4);
        atomicAdd(&sc[g], 1);
    }
    __syncthreads();
    for (int i = threadIdx.x; i < G * 5; i += blockDim.x) atomicAdd(&gsum[i], ss[i]);
    for (int i = threadIdx.x; i < G; i += blockDim.x) atomicAdd(&gcnt[i], sc[i]);
}

// ---------------- row-tiled skinny GEMM: Y[M,NOUT] = X[M,K] @ W[K,NW] ----------------
template <int K, int NOUT, int TC, int RM, int NW>
__global__ void gemm_rm_kernel(const float* __restrict__ X, int xstride,
                               const float* __restrict__ W, const float* __restrict__ bias,
                               float* __restrict__ Y, int ystride, int do_relu, int M) {
    constexpr int TPR = NOUT / TC;      // threads covering one row's columns
    constexpr int RT = 256 / TPR;       // row-thread groups per block
    constexpr int R = RT * RM;          // rows per block
    __shared__ float Ws[K * NOUT];
    for (int i = threadIdx.x; i < K * NOUT; i += 256) {
        int k = i / NOUT, c = i % NOUT;
        Ws[i] = (c < NW) ? W[k * NW + c] : 0.f;
    }
    __syncthreads();
    int rt = threadIdx.x / TPR;
    int c0 = (threadIdx.x % TPR) * TC;
    int r0 = blockIdx.x * R + rt * RM;
    if (r0 >= M) return;
    float acc[RM][TC];
#pragma unroll
    for (int m = 0; m < RM; m++)
#pragma unroll
        for (int t = 0; t < TC; t++) acc[m][t] = 0.f;
#pragma unroll 2
    for (int k = 0; k < K; k++) {
        float xv[RM];
#pragma unroll
        for (int m = 0; m < RM; m++) {
            int r = r0 + m;
            if (r >= M) r = M - 1;
            xv[m] = __ldg(X + (size_t)r * xstride + k);
        }
#pragma unroll
        for (int t = 0; t < TC; t += 4) {
            float4 w = *(const float4*)&Ws[k * NOUT + c0 + t];
#pragma unroll
            for (int m = 0; m < RM; m++) {
                acc[m][t + 0] += xv[m] * w.x;
                acc[m][t + 1] += xv[m] * w.y;
                acc[m][t + 2] += xv[m] * w.z;
                acc[m][t + 3] += xv[m] * w.w;
            }
        }
    }
#pragma unroll
    for (int m = 0; m < RM; m++) {
        int r = r0 + m;
        if (r >= M) break;
#pragma unroll
        for (int t = 0; t < TC; t++) {
            int c = c0 + t;
            float v = acc[m][t];
            if (c < NW) {
                if (bias) v += bias[c];
                if (do_relu) v = fmaxf(v, 0.f);
            }
            Y[(size_t)r * ystride + c] = v;
        }
    }
}

// ---------------- small GEMM (64 -> 5, stride-8 out) ----------------
template <int K, int NOUT, int TC, int NW>
__global__ void gemm_kernel(const float* __restrict__ X, int xstride,
                            const float* __restrict__ W, const float* __restrict__ bias,
                            float* __restrict__ Y, int ystride, int do_relu, int M) {
    constexpr int TPR = NOUT / TC;
    constexpr int R = 256 / TPR;
    __shared__ float Ws[K * NOUT];
    for (int i = threadIdx.x; i < K * NOUT; i += 256) {
        int k = i / NOUT, c = i % NOUT;
        Ws[i] = (c < NW) ? W[k * NW + c] : 0.f;
    }
    __syncthreads();
    int r = blockIdx.x * R + threadIdx.x / TPR;
    int c0 = (threadIdx.x % TPR) * TC;
    if (r >= M) return;
    float acc[TC];
#pragma unroll
    for (int t = 0; t < TC; t++) acc[t] = 0.f;
    const float* xrow = X + (size_t)r * xstride;
#pragma unroll 4
    for (int k = 0; k < K; k++) {
        float xv = __ldg(xrow + k);
#pragma unroll
        for (int t = 0; t < TC; t++) acc[t] += xv * Ws[k * NOUT + c0 + t];
    }
#pragma unroll
    for (int t = 0; t < TC; t++) {
        int c = c0 + t;
        float v = acc[t];
        if (bias && c < NW) v += bias[c];
        if (do_relu) v = fmaxf(v, 0.f);
        Y[(size_t)r * ystride + c] = v;
    }
}

// ---------------- final FC + log_softmax ----------------
__global__ void final_kernel(const float* __restrict__ Wfc, const float* __restrict__ bfc,
                             float* __restrict__ out) {
    int g = threadIdx.x;
    if (g >= G) return;
    float f[10];
    float co = fmaxf((float)gcnt_o[g], 1.f);
    float cl = fmaxf((float)gcnt_l[g], 1.f);
#pragma unroll
    for (int j = 0; j < 5; j++) {
        f[j] = gsum_o[g * 5 + j] / co;
        f[5 + j] = gsum_l[g * 5 + j] / cl;
    }
    float y0 = bfc[0], y1 = bfc[1];
#pragma unroll
    for (int j = 0; j < 10; j++) {
        y0 += f[j] * Wfc[j * 2 + 0];
        y1 += f[j] * Wfc[j * 2 + 1];
    }
    float m = fmaxf(y0, y1);
    float lse = m + logf(expf(y0 - m) + expf(y1 - m));
    out[g * 2 + 0] = y0 - lse;
    out[g * 2 + 1] = y1 - lse;
}

// ---------------- host side ----------------
struct SymPtrs {
    float2 *csr_o_, *csr_l_;
    int *rp_o_, *rp_l_, *cnt_o_, *cnt_l_, *fill_o_, *fill_l_, *gcnt_o_, *gcnt_l_;
    int *bsum_o_, *bsum_l_;
    float *dinv_o_, *dinv_l_;
    float *XPo_, *XPl_, *P1_, *H1_, *T2_, *H2_, *T3_, *PL_, *HL1_, *TL_;
    float *gsum_o_, *gsum_l_;
    cudaStream_t s1, s2;
    cudaEvent_t evRoot, ev1, ev2;
    bool ready;
};
static SymPtrs SP = {};

static void resolve_syms() {
    if (SP.ready) return;
    cudaGetSymbolAddress((void**)&SP.csr_o_, csr_o);
    cudaGetSymbolAddress((void**)&SP.csr_l_, csr_l);
    cudaGetSymbolAddress((void**)&SP.rp_o_, rp_o);
    cudaGetSymbolAddress((void**)&SP.rp_l_, rp_l);
    cudaGetSymbolAddress((void**)&SP.cnt_o_, cnt_o);
    cudaGetSymbolAddress((void**)&SP.cnt_l_, cnt_l);
    cudaGetSymbolAddress((void**)&SP.fill_o_, fill_o);
    cudaGetSymbolAddress((void**)&SP.fill_l_, fill_l);
    cudaGetSymbolAddress((void**)&SP.gcnt_o_, gcnt_o);
    cudaGetSymbolAddress((void**)&SP.gcnt_l_, gcnt_l);
    cudaGetSymbolAddress((void**)&SP.bsum_o_, bsum_o);
    cudaGetSymbolAddress((void**)&SP.bsum_l_, bsum_l);
    cudaGetSymbolAddress((void**)&SP.dinv_o_, dinv_o);
    cudaGetSymbolAddress((void**)&SP.dinv_l_, dinv_l);
    cudaGetSymbolAddress((void**)&SP.XPo_, XPo);
    cudaGetSymbolAddress((void**)&SP.XPl_, XPl);
    cudaGetSymbolAddress((void**)&SP.P1_, P1);
    cudaGetSymbolAddress((void**)&SP.H1_, H1b);
    cudaGetSymbolAddress((void**)&SP.T2_, T2b);
    cudaGetSymbolAddress((void**)&SP.H2_, H2b);
    cudaGetSymbolAddress((void**)&SP.T3_, T3b);
    cudaGetSymbolAddress((void**)&SP.PL_, PLb);
    cudaGetSymbolAddress((void**)&SP.HL1_, HL1b);
    cudaGetSymbolAddress((void**)&SP.TL_, TLb);
    cudaGetSymbolAddress((void**)&SP.gsum_o_, gsum_o);
    cudaGetSymbolAddress((void**)&SP.gsum_l_, gsum_l);
    cudaStreamCreateWithFlags(&SP.s1, cudaStreamNonBlocking);
    cudaStreamCreateWithFlags(&SP.s2, cudaStreamNonBlocking);
    cudaEventCreateWithFlags(&SP.evRoot, cudaEventDisableTiming);
    cudaEventCreateWithFlags(&SP.ev1, cudaEventDisableTiming);
    cudaEventCreateWithFlags(&SP.ev2, cudaEventDisableTiming);
    SP.ready = true;
}

extern "C" void kernel_launch(void* const* d_in, const int* in_sizes, int n_in,
                              void* d_out, int out_size) {
    resolve_syms();

    const float* x_o = (const float*)d_in[0];
    const void* ei_o = d_in[1];
    const void* ba_o = d_in[2];
    const float* x_l = (const float*)d_in[3];
    const void* ei_l = d_in[4];
    const void* ba_l = d_in[5];
    const float* W1 = (const float*)d_in[6];
    const float* b1 = (const float*)d_in[7];
    const float* W2 = (const float*)d_in[8];
    const float* b2 = (const float*)d_in[9];
    const float* W5 = (const float*)d_in[10];
    const float* b5 = (const float*)d_in[11];
    const float* W3 = (const float*)d_in[12];
    const float* b3 = (const float*)d_in[13];
    const float* W4 = (const float*)d_in[14];
    const float* b4 = (const float*)d_in[15];
    const float* Wfc = (const float*)d_in[16];
    const float* bfc = (const float*)d_in[17];
    float* out = (float*)d_out;

    int N = in_sizes[0] / 25;
    long long E = (long long)in_sizes[1] / 2;
    int SB = (N + 1023) / 1024;        // scan blocks
    int pb16 = (N * 16 + 255) / 256;   // GROUP=16 prop blocks (2 nodes/warp)
    int pb8v = (N * 8 + 255) / 256;    // GROUP=8 prop blocks (4 nodes/warp)

    // common prologue on the capture stream
    detect_kernel<<<1, 32>>>((const unsigned*)ei_o);
    init_kernel<<<256, 256>>>(N);

    // fork
    cudaEventRecord(SP.evRoot, 0);
    cudaStreamWaitEvent(SP.s1, SP.evRoot, 0);
    cudaStreamWaitEvent(SP.s2, SP.evRoot, 0);

    // ---- origin branch (s1) ----
    pad_kernel<<<2048, 256, 0, SP.s1>>>(x_o, 25, SP.XPo_, 32, (long long)N * 32);
    hist_kernel<<<512, 256, 0, SP.s1>>>(ei_o, E, SP.cnt_o_);
    scan1_kernel<<<SB, 1024, 0, SP.s1>>>(SP.cnt_o_, SP.dinv_o_, SP.bsum_o_, N);
    scan2_kernel<<<1, 128, 0, SP.s1>>>(SP.bsum_o_, SP.rp_o_, SB, N);
    scan3_kernel<<<SB, 1024, 0, SP.s1>>>(SP.cnt_o_, SP.bsum_o_, SP.rp_o_, N);
    scatter_kernel<<<512, 256, 0, SP.s1>>>(ei_o, E, SP.rp_o_, SP.fill_o_, SP.dinv_o_, SP.csr_o_);
    prop4_kernel<8><<<pb8v, 256, 0, SP.s1>>>(SP.XPo_, SP.P1_, SP.rp_o_, SP.csr_o_,
                                             SP.dinv_o_, nullptr, 0, N);
    gemm_rm_kernel<25, 128, 8, 4, 128><<<(N + 63) / 64, 256, 0, SP.s1>>>(
        SP.P1_, 32, W1, b1, SP.H1_, 128, 1, N);
    gemm_rm_kernel<128, 64, 8, 4, 64><<<(N + 127) / 128, 256, 0, SP.s1>>>(
        SP.H1_, 128, W2, nullptr, SP.T2_, 64, 0, N);
    prop4_kernel<16><<<pb16, 256, 0, SP.s1>>>(SP.T2_, SP.H2_, SP.rp_o_, SP.csr_o_,
                                              SP.dinv_o_, b2, 1, N);
    gemm_kernel<64, 8, 1, 5><<<(N + 31) / 32, 256, 0, SP.s1>>>(
        SP.H2_, 64, W5, nullptr, SP.T3_, 8, 0, N);
    prop_pool_kernel<<<512, 256, 0, SP.s1>>>(SP.T3_, SP.rp_o_, SP.csr_o_, SP.dinv_o_, b5,
                                             ba_o, SP.gsum_o_, SP.gcnt_o_, N);

    // ---- line branch (s2) ----
    pad_kernel<<<2048, 256, 0, SP.s2>>>(x_l, 51, SP.XPl_, 64, (long long)N * 64);
    hist_kernel<<<512, 256, 0, SP.s2>>>(ei_l, E, SP.cnt_l_);
    scan1_kernel<<<SB, 1024, 0, SP.s2>>>(SP.cnt_l_, SP.dinv_l_, SP.bsum_l_, N);
    scan2_kernel<<<1, 128, 0, SP.s2>>>(SP.bsum_l_, SP.rp_l_, SB, N);
    scan3_kernel<<<SB, 1024, 0, SP.s2>>>(SP.cnt_l_, SP.bsum_l_, SP.rp_l_, N);
    scatter_kernel<<<512, 256, 0, SP.s2>>>(ei_l, E, SP.rp_l_, SP.fill_l_, SP.dinv_l_, SP.csr_l_);
    prop4_kernel<16><<<pb16, 256, 0, SP.s2>>>(SP.XPl_, SP.PL_, SP.rp_l_, SP.csr_l_,
                                              SP.dinv_l_, nullptr, 0, N);
    gemm_rm_kernel<51, 64, 8, 4, 64><<<(N + 127) / 128, 256, 0, SP.s2>>>(
        SP.PL_, 64, W3, b3, SP.HL1_, 64, 1, N);
    gemm_kernel<64, 8, 1, 5><<<(N + 31) / 32, 256, 0, SP.s2>>>(
        SP.HL1_, 64, W4, nullptr, SP.TL_, 8, 0, N);
    prop_pool_kernel<<<512, 256, 0, SP.s2>>>(SP.TL_, SP.rp_l_, SP.csr_l_, SP.dinv_l_, b4,
                                             ba_l, SP.gsum_l_, SP.gcnt_l_, N);

    // join
    cudaEventRecord(SP.ev1, SP.s1);
    cudaEventRecord(SP.ev2, SP.s2);
    cudaStreamWaitEvent(0, SP.ev1, 0);
    cudaStreamWaitEvent(0, SP.ev2, 0);

    final_kernel<<<1, G>>>(Wfc, bfc, out);
}